// round 17
// baseline (speedup 1.0000x reference)
#include <cuda_runtime.h>
#include <cuda_bf16.h>
#include <math.h>
#include <stdint.h>

typedef unsigned long long ULL;
typedef unsigned int uint;

// ---------------- constants ----------------
#define B_   64
#define TT   63          // time steps actually computed (T-1)
#define EE   512
#define HH   1024
#define VV   32000
#define G4   4096        // 4*H
#define KPK  6144        // 6-term split K for tensor projection
#define NKB  96          // 6144 / 64 k-blocks

// ---------------- scratch (device globals; no allocation) ----------------
__device__ __align__(16) float g_Wih0p[G4 * EE];
__device__ __align__(16) float g_Whh0p[G4 * HH];
__device__ __align__(16) float g_W1cat[G4 * 2 * HH];
__device__ __align__(16) float g_b0p[G4];
__device__ __align__(16) float g_b1p[G4];
__device__ __align__(16) float g_G0x[TT * B_ * G4];
__device__ __align__(16) float g_h0buf[2][B_ * HH];
__device__ __align__(16) float g_h1buf[2][B_ * HH];
__device__ __align__(16) float g_c0s[B_ * HH];
__device__ __align__(16) float g_c1s[B_ * HH];
__device__ __align__(16) ULL   g_keys[TT * B_];
__device__ __align__(16) __nv_bfloat16 g_Ahat[(size_t)4096 * KPK];    //  50 MB split H1 (rows >= 4032 stay zero)
__device__ __align__(16) __nv_bfloat16 g_Bhat[(size_t)VV   * KPK];    // 393 MB split proj_W

// ---------------- generic helpers ----------------
static __device__ __forceinline__ void fma2(ULL& acc, ULL a, ULL b) {
    asm("fma.rn.f32x2 %0, %1, %2, %0;" : "+l"(acc) : "l"(a), "l"(b));
}
static __device__ __forceinline__ ULL mk2(float x, float y) {
    ULL r;
    asm("mov.b64 %0, {%1, %2};" : "=l"(r)
        : "r"(__float_as_uint(x)), "r"(__float_as_uint(y)));
    return r;
}
static __device__ __forceinline__ float selh(ULL u, int hi) {
    return __uint_as_float(hi ? (unsigned)(u >> 32) : (unsigned)u);
}
static __device__ __forceinline__ float foldp(ULL u) { return selh(u,0) + selh(u,1); }
static __device__ __forceinline__ ULL dup2(float b) {
    ULL r; unsigned u = __float_as_uint(b);
    asm("mov.b64 %0, {%1, %1};" : "=l"(r) : "r"(u));
    return r;
}
static __device__ __forceinline__ float sigf(float x) { return 1.0f / (1.0f + expf(-x)); }
static __device__ __forceinline__ unsigned fordu(float v) {
    unsigned u = __float_as_uint(v);
    return u ^ (((int)u >> 31) | 0x80000000u);
}
static __device__ __forceinline__ ULL mkkey(float v, int col) {
    return ((ULL)fordu(v) << 32) | (ULL)(0xFFFFFFFFu - (unsigned)col);
}
static __device__ __forceinline__ int bcol(int c) { return c + ((c >> 4) << 1); }

// ---------------- sm_80-level tensor helpers ----------------
static __device__ __forceinline__ uint32_t smem_u32(const void* p) {
    uint32_t a;
    asm("{ .reg .u64 t; cvta.to.shared.u64 t, %1; cvt.u32.u64 %0, t; }" : "=r"(a) : "l"(p));
    return a;
}
static __device__ __forceinline__ void ldsm4(uint32_t* r, uint32_t addr) {
    asm volatile("ldmatrix.sync.aligned.m8n8.x4.shared.b16 {%0,%1,%2,%3}, [%4];"
        : "=r"(r[0]), "=r"(r[1]), "=r"(r[2]), "=r"(r[3]) : "r"(addr));
}
static __device__ __forceinline__ void mma16816(float* c, const uint32_t* a, const uint32_t* b) {
    asm volatile("mma.sync.aligned.m16n8k16.row.col.f32.bf16.bf16.f32 "
        "{%0,%1,%2,%3}, {%4,%5,%6,%7}, {%8,%9}, {%0,%1,%2,%3};"
        : "+f"(c[0]), "+f"(c[1]), "+f"(c[2]), "+f"(c[3])
        : "r"(a[0]), "r"(a[1]), "r"(a[2]), "r"(a[3]), "r"(b[0]), "r"(b[1]));
}
#define CP_ASYNC16(sm, gp) \
    asm volatile("cp.async.cg.shared.global [%0], [%1], 16;" :: "r"(sm), "l"(gp) : "memory")
#define CP_COMMIT() asm volatile("cp.async.commit_group;" ::: "memory")
#define CP_WAIT2()  asm volatile("cp.async.wait_group 2;" ::: "memory")

// ---------------- 1) pack / init ----------------
__global__ void pack_kernel(const float* __restrict__ Wih0, const float* __restrict__ Whh0,
                            const float* __restrict__ Wih1, const float* __restrict__ Whh1,
                            const float* __restrict__ bih0, const float* __restrict__ bhh0,
                            const float* __restrict__ bih1, const float* __restrict__ bhh1) {
    int i = blockIdx.x * 256 + threadIdx.x;
    if (i < TT * B_) g_keys[i] = 0ull;
    int rp  = i >> 11;
    int k   = i & 2047;
    int old = ((rp & 3) << 10) + (rp >> 2);
    g_W1cat[i] = (k < HH) ? Wih1[old * HH + k] : Whh1[old * HH + (k - HH)];
    if (k < EE) g_Wih0p[rp * EE + k] = Wih0[old * EE + k];
    if (k < HH) g_Whh0p[rp * HH + k] = Whh0[old * HH + k];
    if (k == 0) {
        g_b0p[rp] = bih0[old] + bhh0[old];
        g_b1p[rp] = bih1[old] + bhh1[old];
    }
}

// ---------------- 1b) split packer for proj_W ----------------
__global__ void packB_kernel(const float* __restrict__ PW) {
    int i = blockIdx.x * 256 + threadIdx.x;           // over 32000*1024
    int k = i & 1023;
    float x = PW[i];
    __nv_bfloat16 h = __float2bfloat16(x);
    float fh = __bfloat162float(h);
    __nv_bfloat16 m = __float2bfloat16(x - fh);
    float fm = __bfloat162float(m);
    __nv_bfloat16 l = __float2bfloat16(x - fh - fm);
    size_t base = (size_t)(i >> 10) * KPK + k;
    // B segs: [h, h, m, h, l, m]
    g_Bhat[base         ] = h;
    g_Bhat[base + 1024  ] = h;
    g_Bhat[base + 2048  ] = m;
    g_Bhat[base + 3072  ] = h;
    g_Bhat[base + 4096  ] = l;
    g_Bhat[base + 5120  ] = m;
}

// ---------------- 2) h0 init ----------------
__global__ __launch_bounds__(128) void h0init_kernel(const float* __restrict__ S,
                                                     const float* __restrict__ EW) {
    __shared__ float A_sm[32 * 66];
    __shared__ float B_sm[32 * 36];
    int tid = threadIdx.x, tr = tid >> 3, tc = tid & 7;
    int cb = blockIdx.x * 32;
    ULL acc[2][4] = {{0,0,0,0},{0,0,0,0}};
    float pA[16], pB[8];
    #pragma unroll
    for (int e = 0; e < 16; e++) { int idx = e*128+tid; pA[e] = S[(idx>>5)*2048 + (idx&31)]; }
    #pragma unroll
    for (int e = 0; e < 8;  e++) { int idx = e*128+tid; pB[e] = EW[(size_t)(cb+(idx>>5))*2048 + (idx&31)]; }
    for (int k0 = 0; k0 < 2048; k0 += 32) {
        __syncthreads();
        #pragma unroll
        for (int e = 0; e < 16; e++) { int idx = e*128+tid; A_sm[(idx&31)*66 + (idx>>5)] = pA[e]; }
        #pragma unroll
        for (int e = 0; e < 8;  e++) { int idx = e*128+tid; B_sm[(idx&31)*36 + (idx>>5)] = pB[e]; }
        __syncthreads();
        int kn = k0 + 32;
        if (kn < 2048) {
            #pragma unroll
            for (int e = 0; e < 16; e++) { int idx = e*128+tid; pA[e] = S[(idx>>5)*2048 + kn + (idx&31)]; }
            #pragma unroll
            for (int e = 0; e < 8;  e++) { int idx = e*128+tid; pB[e] = EW[(size_t)(cb+(idx>>5))*2048 + kn + (idx&31)]; }
        }
        #pragma unroll 8
        for (int kk = 0; kk < 32; kk++) {
            const ULL* ar = reinterpret_cast<const ULL*>(A_sm + kk * 66);
            ULL a0 = ar[2*tr], a1 = ar[2*tr+1];
            float4 bv = *reinterpret_cast<const float4*>(B_sm + kk*36 + 4*tc);
            ULL b0 = dup2(bv.x), b1 = dup2(bv.y), b2 = dup2(bv.z), b3 = dup2(bv.w);
            fma2(acc[0][0], a0, b0); fma2(acc[1][0], a1, b0);
            fma2(acc[0][1], a0, b1); fma2(acc[1][1], a1, b1);
            fma2(acc[0][2], a0, b2); fma2(acc[1][2], a1, b2);
            fma2(acc[0][3], a0, b3); fma2(acc[1][3], a1, b3);
        }
    }
    #pragma unroll
    for (int p = 0; p < 2; p++)
        #pragma unroll
        for (int hi = 0; hi < 2; hi++) {
            int r = 4*tr + 2*p + hi;
            #pragma unroll
            for (int c = 0; c < 4; c++) {
                int col = cb + 4*tc + c;
                float v = selh(acc[p][c], hi);
                g_h0buf[0][r*HH + col] = v;
                g_c0s   [r*HH + col]   = v;
                g_h1buf[0][r*HH + col] = v;
                g_c1s   [r*HH + col]   = v;
            }
        }
}

// ---------------- 3) embx ----------------
__global__ __launch_bounds__(256, 2) void embx_kernel(const int* __restrict__ ids,
                                                      const float* __restrict__ emb) {
    __shared__ ULL A2s[16 * 66];
    __shared__ ULL B2s[16 * 142];
    __shared__ int ids_sm[B_];
    int tid = threadIdx.x, ty = tid >> 5, tx = tid & 31;
    int t = blockIdx.x, cb = blockIdx.y * 128;
    if (tid < B_) ids_sm[tid] = ids[tid * 64 + t];
    __syncthreads();
    ULL acc[8][4];
    #pragma unroll
    for (int r = 0; r < 8; r++)
        #pragma unroll
        for (int c = 0; c < 4; c++) acc[r][c] = 0ull;
    int kp_l = tid & 15, lr = tid >> 4;
    uint aG[4];
    #pragma unroll
    for (int e = 0; e < 4; e++) aG[e] = (uint)ids_sm[lr + 16*e] * EE + 2*kp_l;
    uint bG = (uint)(cb + lr) * EE + 2*kp_l;
    int aS = kp_l*66 + lr;
    int bSb = kp_l*142;
    int bE[8];
    #pragma unroll
    for (int e = 0; e < 8; e++) bE[e] = bcol(lr + 16*e);
    int e0 = bcol(4*tx), e1 = bcol(4*tx + 2);
    float2 pA[4], pB[8];
    #pragma unroll
    for (int e = 0; e < 4; e++) pA[e] = *reinterpret_cast<const float2*>(emb + aG[e]);
    #pragma unroll
    for (int e = 0; e < 8; e++) pB[e] = *reinterpret_cast<const float2*>(g_Wih0p + bG + (uint)(16*e)*EE);
    for (int k0 = 0; k0 < EE; k0 += 32) {
        __syncthreads();
        #pragma unroll
        for (int e = 0; e < 4; e++) A2s[aS + 16*e]  = *reinterpret_cast<ULL*>(&pA[e]);
        #pragma unroll
        for (int e = 0; e < 8; e++) B2s[bSb + bE[e]] = *reinterpret_cast<ULL*>(&pB[e]);
        __syncthreads();
        int kn = k0 + 32;
        if (kn < EE) {
            #pragma unroll
            for (int e = 0; e < 4; e++) pA[e] = *reinterpret_cast<const float2*>(emb + aG[e] + kn);
            #pragma unroll
            for (int e = 0; e < 8; e++) pB[e] = *reinterpret_cast<const float2*>(g_Wih0p + bG + kn + (uint)(16*e)*EE);
        }
        #pragma unroll
        for (int kp = 0; kp < 16; kp++) {
            ulonglong2 b0v = *reinterpret_cast<const ulonglong2*>(&B2s[kp*142 + e0]);
            ulonglong2 b1v = *reinterpret_cast<const ulonglong2*>(&B2s[kp*142 + e1]);
            #pragma unroll
            for (int j = 0; j < 4; j++) {
                ulonglong2 av = *reinterpret_cast<const ulonglong2*>(&A2s[kp*66 + 8*ty + 2*j]);
                fma2(acc[2*j  ][0], av.x, b0v.x); fma2(acc[2*j  ][1], av.x, b0v.y);
                fma2(acc[2*j  ][2], av.x, b1v.x); fma2(acc[2*j  ][3], av.x, b1v.y);
                fma2(acc[2*j+1][0], av.y, b0v.x); fma2(acc[2*j+1][1], av.y, b0v.y);
                fma2(acc[2*j+1][2], av.y, b1v.x); fma2(acc[2*j+1][3], av.y, b1v.y);
            }
        }
    }
    float* outp = g_G0x + (size_t)(t * B_) * G4;
    int col0 = cb + 4*tx;
    float4 bb = *reinterpret_cast<const float4*>(g_b0p + col0);
    #pragma unroll
    for (int rr = 0; rr < 8; rr++) {
        int row = 8*ty + rr;
        float4 v;
        v.x = foldp(acc[rr][0]) + bb.x;
        v.y = foldp(acc[rr][1]) + bb.y;
        v.z = foldp(acc[rr][2]) + bb.z;
        v.w = foldp(acc[rr][3]) + bb.w;
        *reinterpret_cast<float4*>(outp + (size_t)row*G4 + col0) = v;
    }
}

// ---------------- 4) fused LSTM cell; layer-1 writes 6-term split of h to g_Ahat ----
__global__ __launch_bounds__(256) void cell_kernel(int t, int layer) {
    __shared__ ULL A2b[2][16 * 66];
    __shared__ ULL B2b[2][16 * 34];
    int tid = threadIdx.x;
    int w = tid >> 5, l = tid & 31;
    int r0 = 8*w + 2*(l >> 3);
    int cg = l & 7;
    int cb = blockIdx.x * 32;
    int in = t & 1, out = in ^ 1;
    const float *A1, *A2g, *W;
    float *cst, *hout;
    int K;
    if (layer == 0) {
        A1 = g_h0buf[in]; A2g = A1; W = g_Whh0p; K = HH;
        cst = g_c0s; hout = g_h0buf[out];
    } else {
        A1 = g_h0buf[out]; A2g = g_h1buf[in]; W = g_W1cat; K = 2 * HH;
        cst = g_c1s; hout = g_h1buf[out];
    }
    int gc0 = cb + 4*cg;
    ULL acc[2][4];
    if (layer == 0) {
        const float* initp = g_G0x + (size_t)(t * B_) * G4;
        float4 i0 = *reinterpret_cast<const float4*>(initp + (size_t)r0     * G4 + gc0);
        float4 i1 = *reinterpret_cast<const float4*>(initp + (size_t)(r0+1) * G4 + gc0);
        acc[0][0] = mk2(i0.x, 0.f); acc[0][1] = mk2(i0.y, 0.f);
        acc[0][2] = mk2(i0.z, 0.f); acc[0][3] = mk2(i0.w, 0.f);
        acc[1][0] = mk2(i1.x, 0.f); acc[1][1] = mk2(i1.y, 0.f);
        acc[1][2] = mk2(i1.z, 0.f); acc[1][3] = mk2(i1.w, 0.f);
    } else {
        float4 bb = *reinterpret_cast<const float4*>(g_b1p + gc0);
        acc[0][0] = mk2(bb.x, 0.f); acc[0][1] = mk2(bb.y, 0.f);
        acc[0][2] = mk2(bb.z, 0.f); acc[0][3] = mk2(bb.w, 0.f);
        acc[1][0] = acc[0][0]; acc[1][1] = acc[0][1];
        acc[1][2] = acc[0][2]; acc[1][3] = acc[0][3];
    }
    int kp_l = l & 15, half = l >> 4;
    int rowA = 2*w + half;
    int colB = w + 8*half;
    uint aBase = (uint)rowA * HH + 2*kp_l;
    uint bBase = (uint)(cb + colB) * K + 2*kp_l;
    int aS = kp_l*66 + rowA;
    int bS0 = kp_l*34 + colB;
    int bS1 = kp_l*34 + colB + 18;
    int e0 = 4*cg + ((cg >= 4) ? 2 : 0);
    int e1 = e0 + 2;
    int nb = K >> 5;
    float2 pA[4], pB[2];
    #pragma unroll
    for (int e = 0; e < 4; e++) pA[e] = *reinterpret_cast<const float2*>(A1 + aBase + (uint)(16*e)*HH);
    pB[0] = *reinterpret_cast<const float2*>(W + bBase);
    pB[1] = *reinterpret_cast<const float2*>(W + bBase + (uint)16*K);
    #pragma unroll
    for (int e = 0; e < 4; e++) A2b[0][aS + 16*e] = *reinterpret_cast<ULL*>(&pA[e]);
    B2b[0][bS0] = *reinterpret_cast<ULL*>(&pB[0]);
    B2b[0][bS1] = *reinterpret_cast<ULL*>(&pB[1]);
    if (nb > 1) {
        #pragma unroll
        for (int e = 0; e < 4; e++) pA[e] = *reinterpret_cast<const float2*>(A1 + 32 + aBase + (uint)(16*e)*HH);
        pB[0] = *reinterpret_cast<const float2*>(W + bBase + 32);
        pB[1] = *reinterpret_cast<const float2*>(W + bBase + 32 + (uint)16*K);
    }
    for (int blk = 0; blk < nb; blk++) {
        __syncthreads();
        int cur = blk & 1, nxt = cur ^ 1;
        if (blk + 1 < nb) {
            #pragma unroll
            for (int e = 0; e < 4; e++) A2b[nxt][aS + 16*e] = *reinterpret_cast<ULL*>(&pA[e]);
            B2b[nxt][bS0] = *reinterpret_cast<ULL*>(&pB[0]);
            B2b[nxt][bS1] = *reinterpret_cast<ULL*>(&pB[1]);
            if (blk + 2 < nb) {
                int k0 = (blk + 2) << 5;
                const float* Asrc = (k0 < HH) ? (A1 + k0) : (A2g + (k0 - HH));
                #pragma unroll
                for (int e = 0; e < 4; e++) pA[e] = *reinterpret_cast<const float2*>(Asrc + aBase + (uint)(16*e)*HH);
                pB[0] = *reinterpret_cast<const float2*>(W + bBase + k0);
                pB[1] = *reinterpret_cast<const float2*>(W + bBase + k0 + (uint)16*K);
            }
        }
        const ULL* Ab = A2b[cur];
        const ULL* Bb = B2b[cur];
        #pragma unroll
        for (int kp = 0; kp < 16; kp++) {
            ulonglong2 av  = *reinterpret_cast<const ulonglong2*>(&Ab[kp*66 + r0]);
            ulonglong2 b0v = *reinterpret_cast<const ulonglong2*>(&Bb[kp*34 + e0]);
            ulonglong2 b1v = *reinterpret_cast<const ulonglong2*>(&Bb[kp*34 + e1]);
            fma2(acc[0][0], av.x, b0v.x); fma2(acc[0][1], av.x, b0v.y);
            fma2(acc[0][2], av.x, b1v.x); fma2(acc[0][3], av.x, b1v.y);
            fma2(acc[1][0], av.y, b0v.x); fma2(acc[1][1], av.y, b0v.y);
            fma2(acc[1][2], av.y, b1v.x); fma2(acc[1][3], av.y, b1v.y);
        }
    }
    int j = (cb >> 2) + cg;
    #pragma unroll
    for (int r = 0; r < 2; r++) {
        int row = r0 + r;
        float iv = foldp(acc[r][0]);
        float fv = foldp(acc[r][1]);
        float gv = foldp(acc[r][2]);
        float ov = foldp(acc[r][3]);
        float cold = cst[row*HH + j];
        float cn = sigf(fv) * cold + sigf(iv) * tanhf(gv);
        float h  = sigf(ov) * tanhf(cn);
        cst [row*HH + j] = cn;
        hout[row*HH + j] = h;
        if (layer == 1) {
            // write 6-term split of h directly (replaces packA): segs [h, m, h, l, h, m]
            size_t base = (size_t)(t * B_ + row) * KPK + j;
            __nv_bfloat16 hh = __float2bfloat16(h);
            float fh = __bfloat162float(hh);
            __nv_bfloat16 mm = __float2bfloat16(h - fh);
            float fm = __bfloat162float(mm);
            __nv_bfloat16 ll = __float2bfloat16(h - fh - fm);
            g_Ahat[base       ] = hh;
            g_Ahat[base + 1024] = mm;
            g_Ahat[base + 2048] = hh;
            g_Ahat[base + 3072] = ll;
            g_Ahat[base + 4096] = hh;
            g_Ahat[base + 5120] = mm;
        }
    }
}

// ---------------- 5) HMMA projection chunk: m-blocks [mbase, mbase+2) ----------------
#define PROJ_SMEM 99328
__global__ __launch_bounds__(256) void proj_mma_kernel(const float* __restrict__ PB,
                                                       float* __restrict__ out, int mbase) {
    extern __shared__ char smp[];
    uint32_t sbase = smem_u32(smp);
    float* bias_sm = (float*)smp;
    int tid = threadIdx.x;
    int wid = tid >> 5, l = tid & 31;
    int wm = wid >> 2, wn = wid & 3;     // warp grid 2(M) x 4(N)
    int m = mbase + blockIdx.x, nt = blockIdx.y;

    if (tid < 32) *(float4*)(bias_sm + 4*tid) = *(const float4*)(PB + nt*128 + 4*tid);

    int fc = tid & 7;
    const char* aGp[4]; const char* bGp[4];
    uint32_t aSo[4], bSo[4];
    #pragma unroll
    for (int e = 0; e < 4; e++) {
        int row = e*32 + (tid >> 3);
        aGp[e] = (const char*)g_Ahat + 2*((size_t)(m*128  + row)*KPK + fc*8);
        bGp[e] = (const char*)g_Bhat + 2*((size_t)(nt*128 + row)*KPK + fc*8);
        uint32_t so = (uint32_t)(row*128 + ((fc ^ (row & 7)) << 4));
        aSo[e] = sbase + 1024  + so;
        bSo[e] = sbase + 50176 + so;
    }

#define PROJ_FILL(stage, kbv) do { \
    uint32_t s16_ = (uint32_t)(stage) * 16384u; \
    size_t ko_ = (size_t)(kbv) * 128; \
    _Pragma("unroll") for (int e_ = 0; e_ < 4; e_++) CP_ASYNC16(aSo[e_] + s16_, aGp[e_] + ko_); \
    _Pragma("unroll") for (int e_ = 0; e_ < 4; e_++) CP_ASYNC16(bSo[e_] + s16_, bGp[e_] + ko_); \
} while(0)

    int hi = l >> 4;
    uint32_t aRow[4], aXor[4];
    #pragma unroll
    for (int mt = 0; mt < 4; mt++) {
        int row = wm*64 + mt*16 + (l & 15);
        aRow[mt] = sbase + 1024 + (uint32_t)(row*128);
        aXor[mt] = (uint32_t)(row & 7);
    }
    uint32_t bRow[2], bXor[2];
    #pragma unroll
    for (int ng = 0; ng < 2; ng++) {
        int row = wn*32 + ng*16 + (l & 15);
        bRow[ng] = sbase + 50176 + (uint32_t)(row*128);
        bXor[ng] = (uint32_t)(row & 7);
    }

    float acc[4][4][4];
    #pragma unroll
    for (int mt = 0; mt < 4; mt++)
        #pragma unroll
        for (int n8 = 0; n8 < 4; n8++)
            #pragma unroll
            for (int q = 0; q < 4; q++) acc[mt][n8][q] = 0.0f;

    PROJ_FILL(0, 0); CP_COMMIT();
    PROJ_FILL(1, 1); CP_COMMIT();
    PROJ_FILL(2, 2); CP_COMMIT();

    #pragma unroll 1
    for (int kb = 0; kb < NKB; kb++) {
        int s = kb % 3;
        uint32_t s16 = (uint32_t)s * 16384u;
        CP_WAIT2();
        __syncthreads();
        #pragma unroll
        for (int kk = 0; kk < 4; kk++) {
            uint32_t a[4][4], b[2][4];
            #pragma unroll
            for (int mt = 0; mt < 4; mt++)
                ldsm4(a[mt], aRow[mt] + s16 + (((uint32_t)(kk*2 + hi) ^ aXor[mt]) << 4));
            #pragma unroll
            for (int ng = 0; ng < 2; ng++)
                ldsm4(b[ng], bRow[ng] + s16 + (((uint32_t)(kk*2 + hi) ^ bXor[ng]) << 4));
            #pragma unroll
            for (int mt = 0; mt < 4; mt++) {
                #pragma unroll
                for (int n8 = 0; n8 < 4; n8++) {
                    uint32_t bb[2] = { b[n8 >> 1][(n8 & 1)], b[n8 >> 1][(n8 & 1) + 2] };
                    mma16816(acc[mt][n8], a[mt], bb);
                }
            }
        }
        __syncthreads();
        if (kb + 3 < NKB) PROJ_FILL(s, kb + 3);
        CP_COMMIT();
    }

    float* lout = out + TT * B_;
    int cloc = wn*32 + (l & 3)*2;
    #pragma unroll
    for (int mt = 0; mt < 4; mt++) {
        #pragma unroll
        for (int h = 0; h < 2; h++) {
            int grow = m*128 + wm*64 + mt*16 + (l >> 2) + 8*h;
            if (grow < TT * B_) {
                int tt = grow >> 6, bb_ = grow & 63;
                float* rowp = lout + ((size_t)bb_ * TT + tt) * VV + nt*128;
                ULL key = 0ull;
                #pragma unroll
                for (int n8 = 0; n8 < 4; n8++) {
                    int lc = cloc + n8*8;
                    float v0 = acc[mt][n8][2*h]   + bias_sm[lc];
                    float v1 = acc[mt][n8][2*h+1] + bias_sm[lc+1];
                    float2 vv; vv.x = v0; vv.y = v1;
                    *(float2*)(rowp + lc) = vv;
                    int gc = nt*128 + lc;
                    ULL k1 = mkkey(v0, gc);
                    ULL k2 = mkkey(v1, gc + 1); if (k2 > k1) k1 = k2;
                    if (k1 > key) key = k1;
                }
                ULL o = __shfl_xor_sync(0xFFFFFFFFu, key, 1); if (o > key) key = o;
                o     = __shfl_xor_sync(0xFFFFFFFFu, key, 2); if (o > key) key = o;
                if ((l & 3) == 0) atomicMax(&g_keys[tt * B_ + bb_], key);
            }
        }
    }
}

// ---------------- 6) finalize preds ----------------
__global__ void preds_kernel(float* __restrict__ out) {
    int i = blockIdx.x * 256 + threadIdx.x;
    if (i >= TT * B_) return;
    ULL k = g_keys[i];
    unsigned col = 0xFFFFFFFFu - (unsigned)(k & 0xFFFFFFFFull);
    int t = i >> 6, b = i & 63;
    out[b * TT + t] = (float)col;
}

// ---------------- launch: forked-stream overlap of recurrence and projection ----
extern "C" void kernel_launch(void* const* d_in, const int* in_sizes, int n_in,
                              void* d_out, int out_size) {
    const int*   ids    = (const int*)  d_in[0];
    const float* istate = (const float*)d_in[1];
    const float* emb    = (const float*)d_in[2];
    const float* encW   = (const float*)d_in[3];
    const float* Wih0   = (const float*)d_in[4];
    const float* Whh0   = (const float*)d_in[5];
    const float* bih0   = (const float*)d_in[6];
    const float* bhh0   = (const float*)d_in[7];
    const float* Wih1   = (const float*)d_in[8];
    const float* Whh1   = (const float*)d_in[9];
    const float* bih1   = (const float*)d_in[10];
    const float* bhh1   = (const float*)d_in[11];
    const float* PW     = (const float*)d_in[12];
    const float* PB     = (const float*)d_in[13];
    float* out = (float*)d_out;

    // init-once stream/events (created on the uncaptured correctness call)
    static cudaStream_t s2 = nullptr;
    static cudaEvent_t evFork = nullptr, evJoin = nullptr, evC[16];
    if (s2 == nullptr) {
        cudaStreamCreateWithFlags(&s2, cudaStreamNonBlocking);
        cudaEventCreateWithFlags(&evFork, cudaEventDisableTiming);
        cudaEventCreateWithFlags(&evJoin, cudaEventDisableTiming);
        for (int c = 0; c < 16; c++) cudaEventCreateWithFlags(&evC[c], cudaEventDisableTiming);
        cudaFuncSetAttribute(proj_mma_kernel, cudaFuncAttributeMaxDynamicSharedMemorySize, PROJ_SMEM);
    }

    // main stream: packing + recurrence
    pack_kernel<<<(G4 * 2048) / 256, 256>>>(Wih0, Whh0, Wih1, Whh1, bih0, bhh0, bih1, bhh1);
    cudaEventRecord(evFork, 0);
    cudaStreamWaitEvent(s2, evFork, 0);
    packB_kernel<<<(VV * 1024) / 256, 256, 0, s2>>>(PW);   // overlaps h0init/embx

    h0init_kernel<<<32, 128>>>(istate, encW);
    embx_kernel<<<dim3(TT, 32), 256>>>(ids, emb);
    for (int t = 0; t < TT; t++) {
        cell_kernel<<<128, 256>>>(t, 0);
        cell_kernel<<<128, 256>>>(t, 1);
        if ((t & 3) == 3) cudaEventRecord(evC[t >> 2], 0);   // steps 4c..4c+3 done
    }
    cudaEventRecord(evC[15], 0);                             // final steps (60..62)

    // proj stream: chunk c covers m-blocks {2c, 2c+1} = steps 4c..4c+3
    for (int c = 0; c < 16; c++) {
        cudaStreamWaitEvent(s2, evC[c], 0);
        proj_mma_kernel<<<dim3(2, 250), 256, PROJ_SMEM, s2>>>(PB, out, 2 * c);
    }
    cudaEventRecord(evJoin, s2);
    cudaStreamWaitEvent(0, evJoin, 0);

    preds_kernel<<<16, 256>>>(out);
}